// round 3
// baseline (speedup 1.0000x reference)
#include <cuda_runtime.h>
#include <math.h>
#include <stdint.h>

// Problem constants
#define CC   16
#define LL   8192
#define SSZ  8191          // L-1
#define EE   512
#define HH   256
#define MMZ  128
#define KSEL 30
#define RR   (CC * SSZ)    // 131056 output rows

// ---------------------------------------------------------------------------
// Scratch + resolved-input state (static device globals; no allocation)
// ---------------------------------------------------------------------------
__device__ int   g_count;                       // number of active rows
__device__ int   g_rows[RR];                    // compacted active row indices
__device__ float g_h[(size_t)RR * HH];          // hidden activations (compacted)
__device__ unsigned long long g_mask_addr;      // resolved mask pointer
__device__ unsigned long long g_W1_addr;        // resolved W1 pointer
__device__ int   g_mask_mode;                   // 1=uint8 bool, 2=int32 bool, 3=float bool

// ---------------------------------------------------------------------------
// Kernel 0: classify the two 131072-element buffers (mask vs W1), detect the
// mask dtype by content, reset compaction counter. 1 thread; deterministic.
// ---------------------------------------------------------------------------
__device__ int classify_mask(const unsigned int* w) {
    bool ok = true;                               // int32 bool: words in {0,1}
    for (int i = 0; i < 256; i++) if (w[i] > 1u) { ok = false; break; }
    if (ok) return 2;
    ok = true;                                    // float bool: 0.0f / 1.0f
    for (int i = 0; i < 256; i++) {
        unsigned v = w[i];
        if (v != 0u && v != 0x3f800000u) { ok = false; break; }
    }
    if (ok) return 3;
    const unsigned char* b = (const unsigned char*)w;   // uint8 bool
    ok = true;
    for (int i = 0; i < 1024; i++) if (b[i] > 1) { ok = false; break; }
    if (ok) return 1;
    return 0;                                     // not a bool mask (=> W1)
}

__global__ void k_detect(const void* pa, const void* pb) {
    g_count = 0;
    int ma = classify_mask((const unsigned int*)pa);
    if (ma) {
        g_mask_addr = (unsigned long long)pa; g_mask_mode = ma;
        g_W1_addr   = (unsigned long long)pb;
    } else {
        int mb = classify_mask((const unsigned int*)pb);
        g_mask_addr = (unsigned long long)pb; g_mask_mode = mb ? mb : 1;
        g_W1_addr   = (unsigned long long)pa;
    }
}

// ---------------------------------------------------------------------------
// Kernel 1: zero the main output region (masked rows stay zero).
// ---------------------------------------------------------------------------
__global__ void k_zero(float* __restrict__ out, int n4) {
    int i = blockIdx.x * blockDim.x + threadIdx.x;
    if (i < n4) reinterpret_cast<float4*>(out)[i] = make_float4(0.f, 0.f, 0.f, 0.f);
}

// ---------------------------------------------------------------------------
// Kernel 2: write kpm output + compact active row indices.
// Block-aggregated compaction: ballot + warp prefix + one atomicAdd per block.
// ---------------------------------------------------------------------------
__device__ __forceinline__ int read_mask(const void* mp, int mode, int idx) {
    if (mode == 2) return ((const int*)mp)[idx] != 0;
    if (mode == 3) return ((const float*)mp)[idx] != 0.0f;
    return ((const unsigned char*)mp)[idx] != 0;
}

__global__ void k_prep(float* __restrict__ kpm_out, int write_kpm) {
    const void* mp = (const void*)g_mask_addr;
    int mode = g_mask_mode;
    int r = blockIdx.x * blockDim.x + threadIdx.x;
    bool act = false;
    if (r < RR) {
        int c = r / SSZ;                         // mask index = c*LL + (s+1) = r + c + 1
        int m = read_mask(mp, mode, r + c + 1);
        if (write_kpm) kpm_out[r] = m ? 1.0f : 0.0f;
        act = (m == 0);
    }
    unsigned bal = __ballot_sync(0xffffffffu, act);
    int lane = threadIdx.x & 31, wid = threadIdx.x >> 5;
    __shared__ int wtot[8];
    __shared__ int wbase;
    if (lane == 0) wtot[wid] = __popc(bal);
    __syncthreads();
    if (threadIdx.x == 0) {
        int s = 0;
        for (int i = 0; i < 8; i++) { int t = wtot[i]; wtot[i] = s; s += t; }
        wbase = atomicAdd(&g_count, s);
    }
    __syncthreads();
    if (act) {
        int pos = wbase + wtot[wid] + __popc(bal & ((1u << lane) - 1u));
        g_rows[pos] = r;
    }
}

// ---------------------------------------------------------------------------
// Kernel 3: GEMM1  h = relu(xs[active] @ W1 + b1)   (Mrows=nact, K=512, N=256)
// BM=128, BN=128, BK=16; 256 threads, 8x8 register microtile.
// ---------------------------------------------------------------------------
__global__ __launch_bounds__(256) void k_gemm1(const float* __restrict__ x,
                                               const float* __restrict__ b1) {
    const float* __restrict__ W1 = (const float*)g_W1_addr;
    int nact = g_count;
    int tileRow = blockIdx.x * 128;
    if (tileRow >= nact) return;
    int n0 = blockIdx.y * 128;

    __shared__ float As[16][128];
    __shared__ float Bs[16][128];
    __shared__ const float* rowp[128];

    int tid = threadIdx.x;
    if (tid < 128) {
        int i = tileRow + tid;
        if (i < nact) {
            int r = g_rows[i];
            int c = r / SSZ;
            rowp[tid] = x + (size_t)(r + c + 1) * EE;
        } else {
            rowp[tid] = x;   // dummy (store guarded later)
        }
    }
    __syncthreads();

    float acc[8][8] = {};
    int tx = tid & 15, ty = tid >> 4;

    for (int k0 = 0; k0 < EE; k0 += 16) {
#pragma unroll
        for (int l = 0; l < 2; l++) {
            int f = tid + l * 256;
            int row = f >> 2;
            int k4  = (f & 3) * 4;
            float4 v = *(const float4*)(rowp[row] + k0 + k4);
            As[k4 + 0][row] = v.x; As[k4 + 1][row] = v.y;
            As[k4 + 2][row] = v.z; As[k4 + 3][row] = v.w;
        }
#pragma unroll
        for (int l = 0; l < 2; l++) {
            int f  = tid + l * 256;
            int kk = f >> 5;
            int c4 = (f & 31) * 4;
            *(float4*)&Bs[kk][c4] = *(const float4*)&W1[(size_t)(k0 + kk) * HH + n0 + c4];
        }
        __syncthreads();
#pragma unroll
        for (int k = 0; k < 16; k++) {
            float4 a0 = *(float4*)&As[k][ty * 8];
            float4 a1 = *(float4*)&As[k][ty * 8 + 4];
            float4 b0 = *(float4*)&Bs[k][tx * 8];
            float4 b1v = *(float4*)&Bs[k][tx * 8 + 4];
            float a[8] = {a0.x, a0.y, a0.z, a0.w, a1.x, a1.y, a1.z, a1.w};
            float b[8] = {b0.x, b0.y, b0.z, b0.w, b1v.x, b1v.y, b1v.z, b1v.w};
#pragma unroll
            for (int i = 0; i < 8; i++)
#pragma unroll
                for (int j = 0; j < 8; j++)
                    acc[i][j] = fmaf(a[i], b[j], acc[i][j]);
        }
        __syncthreads();
    }

    float4 bb0 = *(const float4*)&b1[n0 + tx * 8];
    float4 bb1 = *(const float4*)&b1[n0 + tx * 8 + 4];
    float bv[8] = {bb0.x, bb0.y, bb0.z, bb0.w, bb1.x, bb1.y, bb1.z, bb1.w};
#pragma unroll
    for (int i = 0; i < 8; i++) {
        int gi = tileRow + ty * 8 + i;
        if (gi < nact) {
            float4 o0, o1;
            o0.x = fmaxf(acc[i][0] + bv[0], 0.f);
            o0.y = fmaxf(acc[i][1] + bv[1], 0.f);
            o0.z = fmaxf(acc[i][2] + bv[2], 0.f);
            o0.w = fmaxf(acc[i][3] + bv[3], 0.f);
            o1.x = fmaxf(acc[i][4] + bv[4], 0.f);
            o1.y = fmaxf(acc[i][5] + bv[5], 0.f);
            o1.z = fmaxf(acc[i][6] + bv[6], 0.f);
            o1.w = fmaxf(acc[i][7] + bv[7], 0.f);
            *(float4*)&g_h[(size_t)gi * HH + n0 + tx * 8]     = o0;
            *(float4*)&g_h[(size_t)gi * HH + n0 + tx * 8 + 4] = o1;
        }
    }
}

// ---------------------------------------------------------------------------
// Warp reductions
// ---------------------------------------------------------------------------
__device__ __forceinline__ float wredmax(float v) {
#pragma unroll
    for (int o = 16; o > 0; o >>= 1) v = fmaxf(v, __shfl_xor_sync(0xffffffffu, v, o));
    return v;
}
__device__ __forceinline__ float wredsum(float v) {
#pragma unroll
    for (int o = 16; o > 0; o >>= 1) v += __shfl_xor_sync(0xffffffffu, v, o);
    return v;
}

// ---------------------------------------------------------------------------
// Kernel 4: GEMM2 + epilogue (gumbel, softmax, exact top-30 threshold,
// sigmoid mask). BM=64, BN=128(full M), BK=16; 128 threads.
// ---------------------------------------------------------------------------
__global__ __launch_bounds__(128) void k_gemm2(const float* __restrict__ W2,
                                               const float* __restrict__ b2,
                                               const float* __restrict__ noise,
                                               float* __restrict__ out) {
    int nact = g_count;
    int tileRow = blockIdx.x * 64;
    if (tileRow >= nact) return;

    __shared__ float As2[16][64];
    __shared__ float Bs2[16][128];
    __shared__ float LS[64][128];     // perturbed logits
    __shared__ int   rs[64];

    int tid = threadIdx.x;
    if (tid < 64) {
        int i = tileRow + tid;
        rs[tid] = (i < nact) ? g_rows[i] : 0;
    }
    __syncthreads();

    float acc[8][8] = {};
    int tx = tid & 15, ty = tid >> 4;

    for (int k0 = 0; k0 < HH; k0 += 16) {
#pragma unroll
        for (int l = 0; l < 2; l++) {
            int f = tid + l * 128;
            int row = f >> 2;
            int k4  = (f & 3) * 4;
            float4 v = *(const float4*)&g_h[(size_t)(tileRow + row) * HH + k0 + k4];
            As2[k4 + 0][row] = v.x; As2[k4 + 1][row] = v.y;
            As2[k4 + 2][row] = v.z; As2[k4 + 3][row] = v.w;
        }
#pragma unroll
        for (int l = 0; l < 4; l++) {
            int f  = tid + l * 128;
            int kk = f >> 5;
            int c4 = (f & 31) * 4;
            *(float4*)&Bs2[kk][c4] = *(const float4*)&W2[(size_t)(k0 + kk) * MMZ + c4];
        }
        __syncthreads();
#pragma unroll
        for (int k = 0; k < 16; k++) {
            float4 a0 = *(float4*)&As2[k][ty * 8];
            float4 a1 = *(float4*)&As2[k][ty * 8 + 4];
            float4 b0 = *(float4*)&Bs2[k][tx * 8];
            float4 b1v = *(float4*)&Bs2[k][tx * 8 + 4];
            float a[8] = {a0.x, a0.y, a0.z, a0.w, a1.x, a1.y, a1.z, a1.w};
            float b[8] = {b0.x, b0.y, b0.z, b0.w, b1v.x, b1v.y, b1v.z, b1v.w};
#pragma unroll
            for (int i = 0; i < 8; i++)
#pragma unroll
                for (int j = 0; j < 8; j++)
                    acc[i][j] = fmaf(a[i], b[j], acc[i][j]);
        }
        __syncthreads();
    }

    // Stage perturbed = acc + b2 + gumbel into LS
#pragma unroll
    for (int i = 0; i < 8; i++) {
        int rowl = ty * 8 + i;
        const float* np_ = noise + (size_t)rs[rowl] * MMZ;
#pragma unroll
        for (int j = 0; j < 8; j += 4) {
            int n = tx * 8 + j;
            float4 u  = *(const float4*)(np_ + n);
            float4 bb = *(const float4*)(b2 + n);
            float4 o;
            o.x = acc[i][j + 0] + bb.x - logf(-logf(u.x + 1e-20f) + 1e-20f);
            o.y = acc[i][j + 1] + bb.y - logf(-logf(u.y + 1e-20f) + 1e-20f);
            o.z = acc[i][j + 2] + bb.z - logf(-logf(u.z + 1e-20f) + 1e-20f);
            o.w = acc[i][j + 3] + bb.w - logf(-logf(u.w + 1e-20f) + 1e-20f);
            *(float4*)&LS[rowl][n] = o;
        }
    }
    __syncthreads();

    // Epilogue: warp per row
    int lane = tid & 31, warp = tid >> 5;
    for (int rowl = warp; rowl < 64; rowl += 4) {
        int gi = tileRow + rowl;
        if (gi >= nact) continue;               // uniform per warp
        int r = rs[rowl];

        float v[4];
#pragma unroll
        for (int i = 0; i < 4; i++) v[i] = LS[rowl][lane + i * 32];

        float mx = fmaxf(fmaxf(v[0], v[1]), fmaxf(v[2], v[3]));
        mx = wredmax(mx);
        float e[4], s = 0.f;
#pragma unroll
        for (int i = 0; i < 4; i++) { e[i] = expf(v[i] - mx); s += e[i]; }
        s = wredsum(s);
        float inv = 1.0f / s;
        float p[4];
#pragma unroll
        for (int i = 0; i < 4; i++) p[i] = e[i] * inv;

        // exact 30th-largest via 30 warp-max extractions (tie-safe)
        float t[4] = {p[0], p[1], p[2], p[3]};
        float thr = 0.f;
        for (int it = 0; it < KSEL; it++) {
            float lm = fmaxf(fmaxf(t[0], t[1]), fmaxf(t[2], t[3]));
            float wm = wredmax(lm);
            thr = wm;
            unsigned bal = __ballot_sync(0xffffffffu, lm == wm);
            int src = __ffs(bal) - 1;
            if (lane == src) {
                if      (t[0] == wm) t[0] = -1e30f;
                else if (t[1] == wm) t[1] = -1e30f;
                else if (t[2] == wm) t[2] = -1e30f;
                else                 t[3] = -1e30f;
            }
        }

        // stable sigmoid mask + write (active row => kpm factor 1)
        float* op = out + (size_t)r * MMZ;
#pragma unroll
        for (int i = 0; i < 4; i++) {
            float z  = (p[i] - thr) * (1.0f / 0.01f);
            float ez = expf(-fabsf(z));
            float mask = (z >= 0.f) ? 1.0f / (1.0f + ez) : ez / (1.0f + ez);
            op[lane + i * 32] = p[i] * mask;
        }
    }
}

// ---------------------------------------------------------------------------
// Launch: resolve inputs by element count (kpm/W1 disambiguated on-device),
// then detect -> zero -> compact -> GEMM1 -> GEMM2+epilogue.
// ---------------------------------------------------------------------------
extern "C" void kernel_launch(void* const* d_in, const int* in_sizes, int n_in,
                              void* d_out, int out_size) {
    int ix = -1, inoise = -1, ib1 = -1, iW2 = -1, ib2 = -1, iA = -1, iB = -1;
    for (int i = 0; i < n_in; i++) {
        int s = in_sizes[i];
        if      (s == CC * LL * EE)        ix = i;        // 67108864
        else if (s == RR * MMZ)            inoise = i;    // 16775168
        else if (s == HH)                  ib1 = i;       // 256
        else if (s == HH * MMZ)            iW2 = i;       // 32768
        else if (s == MMZ)                 ib2 = i;       // 128
        else if (s == CC * LL)             { if (iA < 0) iA = i; else iB = i; } // kpm & W1
    }
    // positional fallback (dict order) if sizes didn't resolve
    if (ix < 0)     ix = 0;
    if (iA < 0)     iA = 1;
    if (inoise < 0) inoise = 2;
    if (iB < 0)     iB = 3;
    if (ib1 < 0)    ib1 = 4;
    if (iW2 < 0)    iW2 = 5;
    if (ib2 < 0)    ib2 = 6;

    const float* x     = (const float*)d_in[ix];
    const float* noise = (const float*)d_in[inoise];
    const float* b1    = (const float*)d_in[ib1];
    const float* W2    = (const float*)d_in[iW2];
    const float* b2    = (const float*)d_in[ib2];
    float* out = (float*)d_out;

    int write_kpm = (out_size >= RR * MMZ + RR) ? 1 : 0;

    k_detect<<<1, 1>>>(d_in[iA], d_in[iB]);
    k_zero<<<(RR * MMZ / 4 + 255) / 256, 256>>>(out, RR * MMZ / 4);
    k_prep<<<(RR + 255) / 256, 256>>>(out + (size_t)RR * MMZ, write_kpm);
    k_gemm1<<<dim3((RR + 127) / 128, 2), 256>>>(x, b1);
    k_gemm2<<<(RR + 63) / 64, 128>>>(W2, b2, noise, out);
}

// round 4
// speedup vs baseline: 1.7192x; 1.7192x over previous
#include <cuda_runtime.h>
#include <cuda_bf16.h>
#include <math.h>
#include <stdint.h>

// Problem constants
#define CC   16
#define LL   8192
#define SSZ  8191
#define EE   512
#define HH   256
#define MMZ  128
#define KSEL 30
#define RR   (CC * SSZ)    // 131056

// ---------------------------------------------------------------------------
// Scratch + resolved-input state
// ---------------------------------------------------------------------------
__device__ int   g_count;
__device__ int   g_rows[RR];
__device__ __nv_bfloat16 g_hh[(size_t)RR * HH];   // hidden, bf16 hi
__device__ __nv_bfloat16 g_hl[(size_t)RR * HH];   // hidden, bf16 lo
__device__ unsigned long long g_mask_addr;
__device__ unsigned long long g_W1_addr;
__device__ int   g_mask_mode;       // 1=u8 bool, 2=i32 bool, 3=f32 bool

// ---------------------------------------------------------------------------
// bf16 split helpers
// ---------------------------------------------------------------------------
__device__ __forceinline__ float lof(float a) {
    return a - __bfloat162float(__float2bfloat16_rn(a));
}
__device__ __forceinline__ unsigned pk(float a, float b) {
    __nv_bfloat162 p;
    p.x = __float2bfloat16_rn(a);
    p.y = __float2bfloat16_rn(b);
    return reinterpret_cast<unsigned&>(p);
}
__device__ __forceinline__ unsigned smaddr(const void* p) {
    return (unsigned)__cvta_generic_to_shared(p);
}
__device__ __forceinline__ void ldsm4(unsigned* r, unsigned a) {
    asm volatile("ldmatrix.sync.aligned.m8n8.x4.shared.b16 {%0,%1,%2,%3},[%4];"
                 : "=r"(r[0]), "=r"(r[1]), "=r"(r[2]), "=r"(r[3]) : "r"(a));
}
__device__ __forceinline__ void ldsm4t(unsigned* r, unsigned a) {
    asm volatile("ldmatrix.sync.aligned.m8n8.x4.trans.shared.b16 {%0,%1,%2,%3},[%4];"
                 : "=r"(r[0]), "=r"(r[1]), "=r"(r[2]), "=r"(r[3]) : "r"(a));
}
__device__ __forceinline__ void mma16816(float* d, const unsigned* a, const unsigned* b) {
    asm volatile("mma.sync.aligned.m16n8k16.row.col.f32.bf16.bf16.f32 "
                 "{%0,%1,%2,%3},{%4,%5,%6,%7},{%8,%9},{%0,%1,%2,%3};\n"
                 : "+f"(d[0]), "+f"(d[1]), "+f"(d[2]), "+f"(d[3])
                 : "r"(a[0]), "r"(a[1]), "r"(a[2]), "r"(a[3]), "r"(b[0]), "r"(b[1]));
}

// ---------------------------------------------------------------------------
// Kernel 0: parallel detect (mask vs W1, mask dtype) + reset counter.
// ---------------------------------------------------------------------------
__global__ void k_detect(const unsigned* wa, const unsigned* wb) {
    int i = threadIdx.x;                 // 256 threads: 1024 bytes each buffer
    unsigned a = wa[i], b = wb[i];
    int a_i32 = __syncthreads_and(a <= 1u);
    int a_f   = __syncthreads_and(a == 0u || a == 0x3f800000u);
    int a_u8  = __syncthreads_and((a & ~0x01010101u) == 0u);
    int b_i32 = __syncthreads_and(b <= 1u);
    int b_f   = __syncthreads_and(b == 0u || b == 0x3f800000u);
    int b_u8  = __syncthreads_and((b & ~0x01010101u) == 0u);
    if (i == 0) {
        g_count = 0;
        int ma = a_i32 ? 2 : (a_f ? 3 : (a_u8 ? 1 : 0));
        if (ma) {
            g_mask_addr = (unsigned long long)wa; g_mask_mode = ma;
            g_W1_addr   = (unsigned long long)wb;
        } else {
            int mb = b_i32 ? 2 : (b_f ? 3 : (b_u8 ? 1 : 0));
            g_mask_addr = (unsigned long long)wb; g_mask_mode = mb ? mb : 1;
            g_W1_addr   = (unsigned long long)wa;
        }
    }
}

// ---------------------------------------------------------------------------
// Kernel 1: zero output
// ---------------------------------------------------------------------------
__global__ void k_zero(float* __restrict__ out, int n4) {
    int i = blockIdx.x * blockDim.x + threadIdx.x;
    if (i < n4) reinterpret_cast<float4*>(out)[i] = make_float4(0.f, 0.f, 0.f, 0.f);
}

// ---------------------------------------------------------------------------
// Kernel 2: kpm out + compaction
// ---------------------------------------------------------------------------
__device__ __forceinline__ int read_mask(const void* mp, int mode, int idx) {
    if (mode == 2) return ((const int*)mp)[idx] != 0;
    if (mode == 3) return ((const float*)mp)[idx] != 0.0f;
    return ((const unsigned char*)mp)[idx] != 0;
}

__global__ void k_prep(float* __restrict__ kpm_out, int write_kpm) {
    const void* mp = (const void*)g_mask_addr;
    int mode = g_mask_mode;
    int r = blockIdx.x * blockDim.x + threadIdx.x;
    bool act = false;
    if (r < RR) {
        int c = r / SSZ;
        int m = read_mask(mp, mode, r + c + 1);
        if (write_kpm) kpm_out[r] = m ? 1.0f : 0.0f;
        act = (m == 0);
    }
    unsigned bal = __ballot_sync(0xffffffffu, act);
    int lane = threadIdx.x & 31, wid = threadIdx.x >> 5;
    __shared__ int wtot[8];
    __shared__ int wbase;
    if (lane == 0) wtot[wid] = __popc(bal);
    __syncthreads();
    if (threadIdx.x == 0) {
        int s = 0;
        for (int i = 0; i < 8; i++) { int t = wtot[i]; wtot[i] = s; s += t; }
        wbase = atomicAdd(&g_count, s);
    }
    __syncthreads();
    if (act) {
        int pos = wbase + wtot[wid] + __popc(bal & ((1u << lane) - 1u));
        g_rows[pos] = r;
    }
}

// ---------------------------------------------------------------------------
// Kernel 3: GEMM1 via bf16-split mma.sync. BM=128, BN=128(grid.y=2), BK=16,
// double-buffered smem. 256 threads = 8 warps (2M x 4N), warp tile 64x32.
// h = relu(x[active] @ W1 + b1) stored as bf16 hi/lo.
// ---------------------------------------------------------------------------
#define ASTR 24     // A smem stride (bf16 elems) per row of 16
#define BSTR 136    // B smem stride (bf16 elems) per row of 128

__global__ __launch_bounds__(256, 1) void k_gemm1(const float* __restrict__ x,
                                                  const float* __restrict__ b1) {
    const float* __restrict__ W1 = (const float*)g_W1_addr;
    int nact = g_count;
    int tileRow = blockIdx.x * 128;
    if (tileRow >= nact) return;
    int n0g = blockIdx.y * 128;

    __shared__ __align__(16) __nv_bfloat16 Ah[2][128 * ASTR];
    __shared__ __align__(16) __nv_bfloat16 Al[2][128 * ASTR];
    __shared__ __align__(16) __nv_bfloat16 Bh[2][16 * BSTR];
    __shared__ __align__(16) __nv_bfloat16 Bl[2][16 * BSTR];
    __shared__ const float* rowp[128];

    int tid = threadIdx.x, lane = tid & 31, warp = tid >> 5;

    if (tid < 128) {
        int i = tileRow + tid;
        if (i < nact) {
            int r = g_rows[i];
            int c = r / SSZ;
            rowp[tid] = x + (size_t)(r + c + 1) * EE;
        } else {
            rowp[tid] = x;
        }
    }
    __syncthreads();

    int arow = tid >> 1, akoff = (tid & 1) * 8;       // A: 8 floats per thread
    int bk = tid >> 4, bn = (tid & 15) * 8;           // B: 8 floats per thread

    float4 ra0, ra1, rb0, rb1;

    // stage-0 load
    {
        const float* ap = rowp[arow] + akoff;
        ra0 = *(const float4*)ap; ra1 = *(const float4*)(ap + 4);
        const float* bp = &W1[(size_t)bk * HH + n0g + bn];
        rb0 = *(const float4*)bp; rb1 = *(const float4*)(bp + 4);
    }
    // store stage 0
    {
        float av[8] = {ra0.x, ra0.y, ra0.z, ra0.w, ra1.x, ra1.y, ra1.z, ra1.w};
        uint4 h, l;
        h.x = pk(av[0], av[1]); h.y = pk(av[2], av[3]); h.z = pk(av[4], av[5]); h.w = pk(av[6], av[7]);
        l.x = pk(lof(av[0]), lof(av[1])); l.y = pk(lof(av[2]), lof(av[3]));
        l.z = pk(lof(av[4]), lof(av[5])); l.w = pk(lof(av[6]), lof(av[7]));
        *(uint4*)&Ah[0][arow * ASTR + akoff] = h;
        *(uint4*)&Al[0][arow * ASTR + akoff] = l;
        float bv[8] = {rb0.x, rb0.y, rb0.z, rb0.w, rb1.x, rb1.y, rb1.z, rb1.w};
        h.x = pk(bv[0], bv[1]); h.y = pk(bv[2], bv[3]); h.z = pk(bv[4], bv[5]); h.w = pk(bv[6], bv[7]);
        l.x = pk(lof(bv[0]), lof(bv[1])); l.y = pk(lof(bv[2]), lof(bv[3]));
        l.z = pk(lof(bv[4]), lof(bv[5])); l.w = pk(lof(bv[6]), lof(bv[7]));
        *(uint4*)&Bh[0][bk * BSTR + bn] = h;
        *(uint4*)&Bl[0][bk * BSTR + bn] = l;
    }
    __syncthreads();

    float acc[4][4][4] = {};
    int mbase = (warp >> 2) * 64;
    int nbase = (warp & 3) * 32;

    for (int s = 0; s < 32; s++) {
        int k0n = (s + 1) * 16;
        if (s < 31) {                                  // prefetch next stage
            const float* ap = rowp[arow] + k0n + akoff;
            ra0 = *(const float4*)ap; ra1 = *(const float4*)(ap + 4);
            const float* bp = &W1[(size_t)(k0n + bk) * HH + n0g + bn];
            rb0 = *(const float4*)bp; rb1 = *(const float4*)(bp + 4);
        }
        int buf = s & 1;
        // fragments
        unsigned afh[4][4], afl[4][4], bfh[4][2], bfl[4][2];
#pragma unroll
        for (int mi = 0; mi < 4; mi++) {
            int off = (mbase + mi * 16 + (lane & 15)) * ASTR + (lane >> 4) * 8;
            ldsm4(afh[mi], smaddr(&Ah[buf][off]));
            ldsm4(afl[mi], smaddr(&Al[buf][off]));
        }
#pragma unroll
        for (int np = 0; np < 2; np++) {
            int off = (lane & 15) * BSTR + nbase + np * 16 + (lane >> 4) * 8;
            unsigned r4[4];
            ldsm4t(r4, smaddr(&Bh[buf][off]));
            bfh[2 * np][0] = r4[0]; bfh[2 * np][1] = r4[1];
            bfh[2 * np + 1][0] = r4[2]; bfh[2 * np + 1][1] = r4[3];
            ldsm4t(r4, smaddr(&Bl[buf][off]));
            bfl[2 * np][0] = r4[0]; bfl[2 * np][1] = r4[1];
            bfl[2 * np + 1][0] = r4[2]; bfl[2 * np + 1][1] = r4[3];
        }
#pragma unroll
        for (int mi = 0; mi < 4; mi++)
#pragma unroll
            for (int ni = 0; ni < 4; ni++) {
                mma16816(acc[mi][ni], afh[mi], bfh[ni]);
                mma16816(acc[mi][ni], afh[mi], bfl[ni]);
                mma16816(acc[mi][ni], afl[mi], bfh[ni]);
            }
        if (s < 31) {                                  // store next stage
            int nb = buf ^ 1;
            float av[8] = {ra0.x, ra0.y, ra0.z, ra0.w, ra1.x, ra1.y, ra1.z, ra1.w};
            uint4 h, l;
            h.x = pk(av[0], av[1]); h.y = pk(av[2], av[3]); h.z = pk(av[4], av[5]); h.w = pk(av[6], av[7]);
            l.x = pk(lof(av[0]), lof(av[1])); l.y = pk(lof(av[2]), lof(av[3]));
            l.z = pk(lof(av[4]), lof(av[5])); l.w = pk(lof(av[6]), lof(av[7]));
            *(uint4*)&Ah[nb][arow * ASTR + akoff] = h;
            *(uint4*)&Al[nb][arow * ASTR + akoff] = l;
            float bv[8] = {rb0.x, rb0.y, rb0.z, rb0.w, rb1.x, rb1.y, rb1.z, rb1.w};
            h.x = pk(bv[0], bv[1]); h.y = pk(bv[2], bv[3]); h.z = pk(bv[4], bv[5]); h.w = pk(bv[6], bv[7]);
            l.x = pk(lof(bv[0]), lof(bv[1])); l.y = pk(lof(bv[2]), lof(bv[3]));
            l.z = pk(lof(bv[4]), lof(bv[5])); l.w = pk(lof(bv[6]), lof(bv[7]));
            *(uint4*)&Bh[nb][bk * BSTR + bn] = h;
            *(uint4*)&Bl[nb][bk * BSTR + bn] = l;
        }
        __syncthreads();
    }

    // Epilogue: relu(acc + b1) -> split bf16 -> g_hh/g_hl
    int g = lane >> 2, t2 = lane & 3;
#pragma unroll
    for (int mi = 0; mi < 4; mi++) {
#pragma unroll
        for (int ni = 0; ni < 4; ni++) {
            int col = n0g + nbase + ni * 8 + t2 * 2;
            float bb0 = b1[col], bb1 = b1[col + 1];
            int row0 = tileRow + mbase + mi * 16 + g;
            int row1 = row0 + 8;
            if (row0 < nact) {
                float v0 = fmaxf(acc[mi][ni][0] + bb0, 0.f);
                float v1 = fmaxf(acc[mi][ni][1] + bb1, 0.f);
                *(unsigned*)&g_hh[(size_t)row0 * HH + col] = pk(v0, v1);
                *(unsigned*)&g_hl[(size_t)row0 * HH + col] = pk(lof(v0), lof(v1));
            }
            if (row1 < nact) {
                float v0 = fmaxf(acc[mi][ni][2] + bb0, 0.f);
                float v1 = fmaxf(acc[mi][ni][3] + bb1, 0.f);
                *(unsigned*)&g_hh[(size_t)row1 * HH + col] = pk(v0, v1);
                *(unsigned*)&g_hl[(size_t)row1 * HH + col] = pk(lof(v0), lof(v1));
            }
        }
    }
}

// ---------------------------------------------------------------------------
// Warp reductions
// ---------------------------------------------------------------------------
__device__ __forceinline__ float wredmax(float v) {
#pragma unroll
    for (int o = 16; o > 0; o >>= 1) v = fmaxf(v, __shfl_xor_sync(0xffffffffu, v, o));
    return v;
}
__device__ __forceinline__ float wredsum(float v) {
#pragma unroll
    for (int o = 16; o > 0; o >>= 1) v += __shfl_xor_sync(0xffffffffu, v, o);
    return v;
}

// ---------------------------------------------------------------------------
// Kernel 4: GEMM2 (bf16-split mma) + epilogue. BM=64, BN=128, BK=16 single
// buffer. 256 threads = 8 warps (2M x 4N), warp tile 32x32.
// ---------------------------------------------------------------------------
__global__ __launch_bounds__(256, 1) void k_gemm2(const float* __restrict__ W2,
                                                  const float* __restrict__ b2,
                                                  const float* __restrict__ noise,
                                                  float* __restrict__ out) {
    int nact = g_count;
    int tileRow = blockIdx.x * 64;
    if (tileRow >= nact) return;

    __shared__ __align__(16) __nv_bfloat16 Ah[64 * ASTR];
    __shared__ __align__(16) __nv_bfloat16 Al[64 * ASTR];
    __shared__ __align__(16) __nv_bfloat16 Bh[16 * BSTR];
    __shared__ __align__(16) __nv_bfloat16 Bl[16 * BSTR];
    __shared__ float LS[64][128];
    __shared__ int   rs[64];

    int tid = threadIdx.x, lane = tid & 31, warp = tid >> 5;
    if (tid < 64) {
        int i = tileRow + tid;
        rs[tid] = (i < nact) ? g_rows[i] : 0;
    }

    int arow = tid >> 2;                 // A: 64 rows x {hh,hl} x {half}
    int awhich = (tid >> 1) & 1;
    int ahalf = (tid & 1) * 8;
    int bk = tid >> 4, bn = (tid & 15) * 8;

    float acc[2][4][4] = {};
    int mbase = (warp >> 2) * 32;
    int nbase = (warp & 3) * 32;

    for (int s = 0; s < 16; s++) {
        int k0 = s * 16;
        // load A (bf16 already) and B (fp32 -> split)
        const __nv_bfloat16* src = awhich ? g_hl : g_hh;
        uint4 av = *(const uint4*)&src[(size_t)(tileRow + arow) * HH + k0 + ahalf];
        const float* bp = &W2[(size_t)(k0 + bk) * MMZ + bn];
        float4 rb0 = *(const float4*)bp, rb1 = *(const float4*)(bp + 4);
        __syncthreads();            // previous compute done before overwrite
        if (awhich) *(uint4*)&Al[arow * ASTR + ahalf] = av;
        else        *(uint4*)&Ah[arow * ASTR + ahalf] = av;
        {
            float bv[8] = {rb0.x, rb0.y, rb0.z, rb0.w, rb1.x, rb1.y, rb1.z, rb1.w};
            uint4 h, l;
            h.x = pk(bv[0], bv[1]); h.y = pk(bv[2], bv[3]); h.z = pk(bv[4], bv[5]); h.w = pk(bv[6], bv[7]);
            l.x = pk(lof(bv[0]), lof(bv[1])); l.y = pk(lof(bv[2]), lof(bv[3]));
            l.z = pk(lof(bv[4]), lof(bv[5])); l.w = pk(lof(bv[6]), lof(bv[7]));
            *(uint4*)&Bh[bk * BSTR + bn] = h;
            *(uint4*)&Bl[bk * BSTR + bn] = l;
        }
        __syncthreads();
        unsigned afh[2][4], afl[2][4], bfh[4][2], bfl[4][2];
#pragma unroll
        for (int mi = 0; mi < 2; mi++) {
            int off = (mbase + mi * 16 + (lane & 15)) * ASTR + (lane >> 4) * 8;
            ldsm4(afh[mi], smaddr(&Ah[off]));
            ldsm4(afl[mi], smaddr(&Al[off]));
        }
#pragma unroll
        for (int np = 0; np < 2; np++) {
            int off = (lane & 15) * BSTR + nbase + np * 16 + (lane >> 4) * 8;
            unsigned r4[4];
            ldsm4t(r4, smaddr(&Bh[off]));
            bfh[2 * np][0] = r4[0]; bfh[2 * np][1] = r4[1];
            bfh[2 * np + 1][0] = r4[2]; bfh[2 * np + 1][1] = r4[3];
            ldsm4t(r4, smaddr(&Bl[off]));
            bfl[2 * np][0] = r4[0]; bfl[2 * np][1] = r4[1];
            bfl[2 * np + 1][0] = r4[2]; bfl[2 * np + 1][1] = r4[3];
        }
#pragma unroll
        for (int mi = 0; mi < 2; mi++)
#pragma unroll
            for (int ni = 0; ni < 4; ni++) {
                mma16816(acc[mi][ni], afh[mi], bfh[ni]);
                mma16816(acc[mi][ni], afh[mi], bfl[ni]);
                mma16816(acc[mi][ni], afl[mi], bfh[ni]);
            }
    }
    __syncthreads();

    // perturbed = acc + b2 + gumbel -> LS
    int g = lane >> 2, t2 = lane & 3;
#pragma unroll
    for (int mi = 0; mi < 2; mi++) {
#pragma unroll
        for (int ni = 0; ni < 4; ni++) {
            int col = nbase + ni * 8 + t2 * 2;
            float bb0 = b2[col], bb1 = b2[col + 1];
            int rl0 = mbase + mi * 16 + g;
            int rl1 = rl0 + 8;
            {
                const float* np_ = noise + (size_t)rs[rl0] * MMZ + col;
                float u0 = np_[0], u1 = np_[1];
                LS[rl0][col]     = acc[mi][ni][0] + bb0 - logf(-logf(u0 + 1e-20f) + 1e-20f);
                LS[rl0][col + 1] = acc[mi][ni][1] + bb1 - logf(-logf(u1 + 1e-20f) + 1e-20f);
            }
            {
                const float* np_ = noise + (size_t)rs[rl1] * MMZ + col;
                float u0 = np_[0], u1 = np_[1];
                LS[rl1][col]     = acc[mi][ni][2] + bb0 - logf(-logf(u0 + 1e-20f) + 1e-20f);
                LS[rl1][col + 1] = acc[mi][ni][3] + bb1 - logf(-logf(u1 + 1e-20f) + 1e-20f);
            }
        }
    }
    __syncthreads();

    // epilogue: warp per row (8 warps)
    for (int rowl = warp; rowl < 64; rowl += 8) {
        int gi = tileRow + rowl;
        if (gi >= nact) continue;
        int r = rs[rowl];

        float v[4];
#pragma unroll
        for (int i = 0; i < 4; i++) v[i] = LS[rowl][lane + i * 32];

        float mx = fmaxf(fmaxf(v[0], v[1]), fmaxf(v[2], v[3]));
        mx = wredmax(mx);
        float e[4], ssum = 0.f;
#pragma unroll
        for (int i = 0; i < 4; i++) { e[i] = expf(v[i] - mx); ssum += e[i]; }
        ssum = wredsum(ssum);
        float inv = 1.0f / ssum;
        float p[4];
#pragma unroll
        for (int i = 0; i < 4; i++) p[i] = e[i] * inv;

        float t[4] = {p[0], p[1], p[2], p[3]};
        float thr = 0.f;
        for (int it = 0; it < KSEL; it++) {
            float lm = fmaxf(fmaxf(t[0], t[1]), fmaxf(t[2], t[3]));
            float wm = wredmax(lm);
            thr = wm;
            unsigned bal = __ballot_sync(0xffffffffu, lm == wm);
            int src = __ffs(bal) - 1;
            if (lane == src) {
                if      (t[0] == wm) t[0] = -1e30f;
                else if (t[1] == wm) t[1] = -1e30f;
                else if (t[2] == wm) t[2] = -1e30f;
                else                 t[3] = -1e30f;
            }
        }

        float* op = out + (size_t)r * MMZ;
#pragma unroll
        for (int i = 0; i < 4; i++) {
            float z  = (p[i] - thr) * (1.0f / 0.01f);
            float ez = expf(-fabsf(z));
            float mask = (z >= 0.f) ? 1.0f / (1.0f + ez) : ez / (1.0f + ez);
            op[lane + i * 32] = p[i] * mask;
        }
    }
}

// ---------------------------------------------------------------------------
// Launch
// ---------------------------------------------------------------------------
extern "C" void kernel_launch(void* const* d_in, const int* in_sizes, int n_in,
                              void* d_out, int out_size) {
    int ix = -1, inoise = -1, ib1 = -1, iW2 = -1, ib2 = -1, iA = -1, iB = -1;
    for (int i = 0; i < n_in; i++) {
        int s = in_sizes[i];
        if      (s == CC * LL * EE)        ix = i;
        else if (s == RR * MMZ)            inoise = i;
        else if (s == HH)                  ib1 = i;
        else if (s == HH * MMZ)            iW2 = i;
        else if (s == MMZ)                 ib2 = i;
        else if (s == CC * LL)             { if (iA < 0) iA = i; else iB = i; }
    }
    if (ix < 0)     ix = 0;
    if (iA < 0)     iA = 1;
    if (inoise < 0) inoise = 2;
    if (iB < 0)     iB = 3;
    if (ib1 < 0)    ib1 = 4;
    if (iW2 < 0)    iW2 = 5;
    if (ib2 < 0)    ib2 = 6;

    const float* x     = (const float*)d_in[ix];
    const float* noise = (const float*)d_in[inoise];
    const float* b1    = (const float*)d_in[ib1];
    const float* W2    = (const float*)d_in[iW2];
    const float* b2    = (const float*)d_in[ib2];
    float* out = (float*)d_out;

    int write_kpm = (out_size >= RR * MMZ + RR) ? 1 : 0;

    k_detect<<<1, 256>>>((const unsigned*)d_in[iA], (const unsigned*)d_in[iB]);
    k_zero<<<(RR * MMZ / 4 + 255) / 256, 256>>>(out, RR * MMZ / 4);
    k_prep<<<(RR + 255) / 256, 256>>>(out + (size_t)RR * MMZ, write_kpm);
    k_gemm1<<<dim3((RR + 127) / 128, 2), 256>>>(x, b1);
    k_gemm2<<<(RR + 63) / 64, 256>>>(W2, b2, noise, out);
}

// round 13
// speedup vs baseline: 1.8993x; 1.1048x over previous
#include <cuda_runtime.h>
#include <cuda_bf16.h>
#include <math.h>
#include <stdint.h>

// Problem constants
#define CC   16
#define LL   8192
#define SSZ  8191
#define EE   512
#define HH   256
#define MMZ  128
#define KSEL 30
#define RR   (CC * SSZ)    // 131056
#define RRP  131072        // RR padded to 128

#define ASTR 24     // A smem stride (bf16) for 16-wide rows (conflict-free ldsm)
#define BSTR 136    // B smem stride (bf16) for 128-wide rows

// ---------------------------------------------------------------------------
// Scratch (static device globals)
// ---------------------------------------------------------------------------
__device__ int   g_count;
__device__ int   g_rows[RRP];
__device__ __nv_bfloat16 g_xh[(size_t)RRP * EE];   // packed active x, bf16 hi
__device__ __nv_bfloat16 g_xl[(size_t)RRP * EE];   // packed active x, bf16 lo
__device__ __nv_bfloat16 g_hh[(size_t)RRP * HH];   // hidden hi
__device__ __nv_bfloat16 g_hl[(size_t)RRP * HH];   // hidden lo
__device__ __nv_bfloat16 g_w1h[EE * HH], g_w1l[EE * HH];
__device__ __nv_bfloat16 g_w2h[HH * MMZ], g_w2l[HH * MMZ];
__device__ unsigned long long g_mask_addr;
__device__ unsigned long long g_W1_addr;
__device__ int   g_mask_mode;

// ---------------------------------------------------------------------------
// helpers
// ---------------------------------------------------------------------------
__device__ __forceinline__ float lof(float a) {
    return a - __bfloat162float(__float2bfloat16_rn(a));
}
__device__ __forceinline__ unsigned pk(float a, float b) {
    __nv_bfloat162 p;
    p.x = __float2bfloat16_rn(a);
    p.y = __float2bfloat16_rn(b);
    return reinterpret_cast<unsigned&>(p);
}
__device__ __forceinline__ unsigned smaddr(const void* p) {
    return (unsigned)__cvta_generic_to_shared(p);
}
__device__ __forceinline__ void cpa16(unsigned d, const void* s) {
    asm volatile("cp.async.ca.shared.global [%0], [%1], 16;\n" :: "r"(d), "l"(s));
}
__device__ __forceinline__ void cpcommit() { asm volatile("cp.async.commit_group;\n"); }
template<int N> __device__ __forceinline__ void cpwait() {
    asm volatile("cp.async.wait_group %0;\n" :: "n"(N));
}
__device__ __forceinline__ void ldsm4(unsigned* r, unsigned a) {
    asm volatile("ldmatrix.sync.aligned.m8n8.x4.shared.b16 {%0,%1,%2,%3},[%4];"
                 : "=r"(r[0]), "=r"(r[1]), "=r"(r[2]), "=r"(r[3]) : "r"(a));
}
__device__ __forceinline__ void ldsm4t(unsigned* r, unsigned a) {
    asm volatile("ldmatrix.sync.aligned.m8n8.x4.trans.shared.b16 {%0,%1,%2,%3},[%4];"
                 : "=r"(r[0]), "=r"(r[1]), "=r"(r[2]), "=r"(r[3]) : "r"(a));
}
__device__ __forceinline__ void mma16816(float* d, const unsigned* a, const unsigned* b) {
    asm volatile("mma.sync.aligned.m16n8k16.row.col.f32.bf16.bf16.f32 "
                 "{%0,%1,%2,%3},{%4,%5,%6,%7},{%8,%9},{%0,%1,%2,%3};\n"
                 : "+f"(d[0]), "+f"(d[1]), "+f"(d[2]), "+f"(d[3])
                 : "r"(a[0]), "r"(a[1]), "r"(a[2]), "r"(a[3]), "r"(b[0]), "r"(b[1]));
}

// ---------------------------------------------------------------------------
// Kernel 0: parallel detect + reset counter
// ---------------------------------------------------------------------------
__global__ void k_detect(const unsigned* wa, const unsigned* wb) {
    int i = threadIdx.x;
    unsigned a = wa[i], b = wb[i];
    int a_i32 = __syncthreads_and(a <= 1u);
    int a_f   = __syncthreads_and(a == 0u || a == 0x3f800000u);
    int a_u8  = __syncthreads_and((a & ~0x01010101u) == 0u);
    int b_i32 = __syncthreads_and(b <= 1u);
    int b_f   = __syncthreads_and(b == 0u || b == 0x3f800000u);
    int b_u8  = __syncthreads_and((b & ~0x01010101u) == 0u);
    if (i == 0) {
        g_count = 0;
        int ma = a_i32 ? 2 : (a_f ? 3 : (a_u8 ? 1 : 0));
        if (ma) {
            g_mask_addr = (unsigned long long)wa; g_mask_mode = ma;
            g_W1_addr   = (unsigned long long)wb;
        } else {
            int mb = b_i32 ? 2 : (b_f ? 3 : (b_u8 ? 1 : 0));
            g_mask_addr = (unsigned long long)wb; g_mask_mode = mb ? mb : 1;
            g_W1_addr   = (unsigned long long)wa;
        }
    }
}

// ---------------------------------------------------------------------------
// Kernel: pack W1 (from detected ptr) and W2 to bf16 hi/lo
// ---------------------------------------------------------------------------
__global__ void k_pack_w(const float* __restrict__ W2) {
    const float* W1 = (const float*)g_W1_addr;
    int i = blockIdx.x * 256 + threadIdx.x;
    if (i < EE * HH) {
        float v = W1[i];
        g_w1h[i] = __float2bfloat16_rn(v);
        g_w1l[i] = __float2bfloat16_rn(lof(v));
    }
    if (i < HH * MMZ) {
        float v = W2[i];
        g_w2h[i] = __float2bfloat16_rn(v);
        g_w2l[i] = __float2bfloat16_rn(lof(v));
    }
}

// ---------------------------------------------------------------------------
// Kernel 1: zero output
// ---------------------------------------------------------------------------
__global__ void k_zero(float* __restrict__ out, int n4) {
    int i = blockIdx.x * blockDim.x + threadIdx.x;
    if (i < n4) reinterpret_cast<float4*>(out)[i] = make_float4(0.f, 0.f, 0.f, 0.f);
}

// ---------------------------------------------------------------------------
// Kernel 2: kpm out + compaction
// ---------------------------------------------------------------------------
__device__ __forceinline__ int read_mask(const void* mp, int mode, int idx) {
    if (mode == 2) return ((const int*)mp)[idx] != 0;
    if (mode == 3) return ((const float*)mp)[idx] != 0.0f;
    return ((const unsigned char*)mp)[idx] != 0;
}

__global__ void k_prep(float* __restrict__ kpm_out, int write_kpm) {
    const void* mp = (const void*)g_mask_addr;
    int mode = g_mask_mode;
    int r = blockIdx.x * blockDim.x + threadIdx.x;
    bool act = false;
    if (r < RR) {
        int c = r / SSZ;
        int m = read_mask(mp, mode, r + c + 1);
        if (write_kpm) kpm_out[r] = m ? 1.0f : 0.0f;
        act = (m == 0);
    }
    unsigned bal = __ballot_sync(0xffffffffu, act);
    int lane = threadIdx.x & 31, wid = threadIdx.x >> 5;
    __shared__ int wtot[8];
    __shared__ int wbase;
    if (lane == 0) wtot[wid] = __popc(bal);
    __syncthreads();
    if (threadIdx.x == 0) {
        int s = 0;
        for (int i = 0; i < 8; i++) { int t = wtot[i]; wtot[i] = s; s += t; }
        wbase = atomicAdd(&g_count, s);
    }
    __syncthreads();
    if (act) {
        int pos = wbase + wtot[wid] + __popc(bal & ((1u << lane) - 1u));
        g_rows[pos] = r;
    }
}

// ---------------------------------------------------------------------------
// Kernel: pack active x rows (gathered, compacted) into bf16 hi/lo
// 2 rows per 256-thread block; 128 threads x float4 per row.
// ---------------------------------------------------------------------------
__global__ void k_pack_x(const float* __restrict__ x) {
    int i = blockIdx.x * 2 + (threadIdx.x >> 7);
    if (i >= g_count) return;
    int j = threadIdx.x & 127;                 // float4 index
    int r = g_rows[i];
    int c = r / SSZ;
    float4 v = reinterpret_cast<const float4*>(x + (size_t)(r + c + 1) * EE)[j];
    uint2 h, l;
    h.x = pk(v.x, v.y); h.y = pk(v.z, v.w);
    l.x = pk(lof(v.x), lof(v.y)); l.y = pk(lof(v.z), lof(v.w));
    *(uint2*)&g_xh[(size_t)i * EE + j * 4] = h;
    *(uint2*)&g_xl[(size_t)i * EE + j * 4] = l;
}

// ---------------------------------------------------------------------------
// Kernel 3: GEMM1, bf16-split mma, cp.async double-buffer.
// BM=128, BN=128 (grid.y=2), BK=16. 256 threads = 8 warps (2M x 4N), 64x32.
// ---------------------------------------------------------------------------
__global__ __launch_bounds__(256, 2) void k_gemm1(const float* __restrict__ b1) {
    int nact = g_count;
    int tileRow = blockIdx.x * 128;
    if (tileRow >= nact) return;
    int n0g = blockIdx.y * 128;

    __shared__ __align__(16) __nv_bfloat16 Ah[2][128 * ASTR];
    __shared__ __align__(16) __nv_bfloat16 Al[2][128 * ASTR];
    __shared__ __align__(16) __nv_bfloat16 Bh[2][16 * BSTR];
    __shared__ __align__(16) __nv_bfloat16 Bl[2][16 * BSTR];

    int tid = threadIdx.x, lane = tid & 31, warp = tid >> 5;

    // per-thread load slots
    int arow = tid >> 1, ah = (tid & 1) * 8;
    int bk = tid >> 4, bn = (tid & 15) * 8;
    const __nv_bfloat16* axh = &g_xh[(size_t)(tileRow + arow) * EE + ah];
    const __nv_bfloat16* axl = &g_xl[(size_t)(tileRow + arow) * EE + ah];
    const __nv_bfloat16* bwh = &g_w1h[(size_t)bk * HH + n0g + bn];
    const __nv_bfloat16* bwl = &g_w1l[(size_t)bk * HH + n0g + bn];
    unsigned sAh = smaddr(&Ah[0][arow * ASTR + ah]);
    unsigned sAl = smaddr(&Al[0][arow * ASTR + ah]);
    unsigned sBh = smaddr(&Bh[0][bk * BSTR + bn]);
    unsigned sBl = smaddr(&Bl[0][bk * BSTR + bn]);
    const unsigned ABUF = 128 * ASTR * 2;   // bytes between A stage buffers
    const unsigned BBUF = 16 * BSTR * 2;

    // stage 0
    cpa16(sAh, axh); cpa16(sAl, axl); cpa16(sBh, bwh); cpa16(sBl, bwl);
    cpcommit();

    float acc[4][4][4] = {};
    int mbase = (warp >> 2) * 64;
    int nbase = (warp & 3) * 32;

    for (int s = 0; s < 32; s++) {
        cpwait<0>();
        __syncthreads();
        if (s + 1 < 32) {                          // issue next stage
            int k0 = (s + 1) * 16;
            int nb = (s + 1) & 1;
            cpa16(sAh + nb * ABUF, axh + k0);
            cpa16(sAl + nb * ABUF, axl + k0);
            cpa16(sBh + nb * BBUF, bwh + (size_t)k0 * HH);
            cpa16(sBl + nb * BBUF, bwl + (size_t)k0 * HH);
            cpcommit();
        }
        int buf = s & 1;
        unsigned afh[4][4], afl[4][4], bfh[4][2], bfl[4][2];
#pragma unroll
        for (int mi = 0; mi < 4; mi++) {
            int off = (mbase + mi * 16 + (lane & 15)) * ASTR + (lane >> 4) * 8;
            ldsm4(afh[mi], smaddr(&Ah[buf][off]));
            ldsm4(afl[mi], smaddr(&Al[buf][off]));
        }
#pragma unroll
        for (int np = 0; np < 2; np++) {
            int off = (lane & 15) * BSTR + nbase + np * 16 + (lane >> 4) * 8;
            unsigned r4[4];
            ldsm4t(r4, smaddr(&Bh[buf][off]));
            bfh[2 * np][0] = r4[0]; bfh[2 * np][1] = r4[1];
            bfh[2 * np + 1][0] = r4[2]; bfh[2 * np + 1][1] = r4[3];
            ldsm4t(r4, smaddr(&Bl[buf][off]));
            bfl[2 * np][0] = r4[0]; bfl[2 * np][1] = r4[1];
            bfl[2 * np + 1][0] = r4[2]; bfl[2 * np + 1][1] = r4[3];
        }
#pragma unroll
        for (int mi = 0; mi < 4; mi++)
#pragma unroll
            for (int ni = 0; ni < 4; ni++) {
                mma16816(acc[mi][ni], afh[mi], bfh[ni]);
                mma16816(acc[mi][ni], afh[mi], bfl[ni]);
                mma16816(acc[mi][ni], afl[mi], bfh[ni]);
            }
    }

    // epilogue: relu(acc + b1) -> split bf16 -> g_hh/g_hl
    int g = lane >> 2, t2 = lane & 3;
#pragma unroll
    for (int mi = 0; mi < 4; mi++) {
#pragma unroll
        for (int ni = 0; ni < 4; ni++) {
            int col = n0g + nbase + ni * 8 + t2 * 2;
            float bb0 = b1[col], bb1 = b1[col + 1];
            int row0 = tileRow + mbase + mi * 16 + g;
            int row1 = row0 + 8;
            if (row0 < nact) {
                float v0 = fmaxf(acc[mi][ni][0] + bb0, 0.f);
                float v1 = fmaxf(acc[mi][ni][1] + bb1, 0.f);
                *(unsigned*)&g_hh[(size_t)row0 * HH + col] = pk(v0, v1);
                *(unsigned*)&g_hl[(size_t)row0 * HH + col] = pk(lof(v0), lof(v1));
            }
            if (row1 < nact) {
                float v0 = fmaxf(acc[mi][ni][2] + bb0, 0.f);
                float v1 = fmaxf(acc[mi][ni][3] + bb1, 0.f);
                *(unsigned*)&g_hh[(size_t)row1 * HH + col] = pk(v0, v1);
                *(unsigned*)&g_hl[(size_t)row1 * HH + col] = pk(lof(v0), lof(v1));
            }
        }
    }
}

// ---------------------------------------------------------------------------
// Kernel 4: GEMM2 + epilogue. BM=64, BN=128, BK=16, cp.async double-buffer.
// Stage buffers unioned with LS (perturbed logits) to stay under 48KB static.
// 256 threads = 8 warps (2M x 4N), warp tile 32x32.
// ---------------------------------------------------------------------------
#define G2_AH 0
#define G2_AL (G2_AH + 2 * 64 * ASTR * 2)
#define G2_BH (G2_AL + 2 * 64 * ASTR * 2)
#define G2_BL (G2_BH + 2 * 16 * BSTR * 2)
#define G2_END (G2_BL + 2 * 16 * BSTR * 2)
#define G2_SM  (64 * 128 * 4 > G2_END ? 64 * 128 * 4 : G2_END)

__global__ __launch_bounds__(256, 2) void k_gemm2(const float* __restrict__ b2,
                                                  const float* __restrict__ noise,
                                                  float* __restrict__ out) {
    int nact = g_count;
    int tileRow = blockIdx.x * 64;
    if (tileRow >= nact) return;

    __shared__ __align__(16) unsigned char SM[G2_SM];
    __shared__ int rs[64];
    __nv_bfloat16* Ah = (__nv_bfloat16*)(SM + G2_AH);
    __nv_bfloat16* Al = (__nv_bfloat16*)(SM + G2_AL);
    __nv_bfloat16* Bh = (__nv_bfloat16*)(SM + G2_BH);
    __nv_bfloat16* Bl = (__nv_bfloat16*)(SM + G2_BL);
    float* LS = (float*)SM;

    int tid = threadIdx.x, lane = tid & 31, warp = tid >> 5;
    if (tid < 64) {
        int i = tileRow + tid;
        rs[tid] = (i < nact) ? g_rows[i] : 0;
    }

    // load slots: threads 0-127 A-hi, 128-255 A-lo; all threads B-hi + B-lo
    int at = tid & 127;
    int arow = at >> 1, ah = (at & 1) * 8;
    int isAlo = tid >> 7;
    const __nv_bfloat16* asrc = (isAlo ? g_hl : g_hh) + (size_t)(tileRow + arow) * HH + ah;
    unsigned sA = smaddr((isAlo ? Al : Ah) + arow * ASTR + ah);
    int bk = tid >> 4, bn = (tid & 15) * 8;
    const __nv_bfloat16* bsh = &g_w2h[(size_t)bk * MMZ + bn];
    const __nv_bfloat16* bsl = &g_w2l[(size_t)bk * MMZ + bn];
    unsigned sBh = smaddr(Bh + bk * BSTR + bn);
    unsigned sBl = smaddr(Bl + bk * BSTR + bn);
    const unsigned ABUF = 64 * ASTR * 2;
    const unsigned BBUF = 16 * BSTR * 2;

    cpa16(sA, asrc); cpa16(sBh, bsh); cpa16(sBl, bsl);
    cpcommit();

    float acc[2][4][4] = {};
    int mbase = (warp >> 2) * 32;
    int nbase = (warp & 3) * 32;

    for (int s = 0; s < 16; s++) {
        cpwait<0>();
        __syncthreads();
        if (s + 1 < 16) {
            int k0 = (s + 1) * 16;
            int nb = (s + 1) & 1;
            cpa16(sA + nb * ABUF, asrc + k0);
            cpa16(sBh + nb * BBUF, bsh + (size_t)k0 * MMZ);
            cpa16(sBl + nb * BBUF, bsl + (size_t)k0 * MMZ);
            cpcommit();
        }
        int buf = s & 1;
        unsigned afh[2][4], afl[2][4], bfh[4][2], bfl[4][2];
#pragma unroll
        for (int mi = 0; mi < 2; mi++) {
            int off = buf * 64 * ASTR + (mbase + mi * 16 + (lane & 15)) * ASTR + (lane >> 4) * 8;
            ldsm4(afh[mi], smaddr(&Ah[off]));
            ldsm4(afl[mi], smaddr(&Al[off]));
        }
#pragma unroll
        for (int np = 0; np < 2; np++) {
            int off = buf * 16 * BSTR + (lane & 15) * BSTR + nbase + np * 16 + (lane >> 4) * 8;
            unsigned r4[4];
            ldsm4t(r4, smaddr(&Bh[off]));
            bfh[2 * np][0] = r4[0]; bfh[2 * np][1] = r4[1];
            bfh[2 * np + 1][0] = r4[2]; bfh[2 * np + 1][1] = r4[3];
            ldsm4t(r4, smaddr(&Bl[off]));
            bfl[2 * np][0] = r4[0]; bfl[2 * np][1] = r4[1];
            bfl[2 * np + 1][0] = r4[2]; bfl[2 * np + 1][1] = r4[3];
        }
#pragma unroll
        for (int mi = 0; mi < 2; mi++)
#pragma unroll
            for (int ni = 0; ni < 4; ni++) {
                mma16816(acc[mi][ni], afh[mi], bfh[ni]);
                mma16816(acc[mi][ni], afh[mi], bfl[ni]);
                mma16816(acc[mi][ni], afl[mi], bfh[ni]);
            }
    }
    __syncthreads();     // all ldsm done before LS overwrites stage buffers

    // perturbed = acc + b2 + gumbel -> LS
    int g = lane >> 2, t2 = lane & 3;
#pragma unroll
    for (int mi = 0; mi < 2; mi++) {
#pragma unroll
        for (int ni = 0; ni < 4; ni++) {
            int col = nbase + ni * 8 + t2 * 2;
            float bb0 = b2[col], bb1 = b2[col + 1];
            int rl0 = mbase + mi * 16 + g;
            int rl1 = rl0 + 8;
            {
                const float* np_ = noise + (size_t)rs[rl0] * MMZ + col;
                float u0 = np_[0], u1 = np_[1];
                LS[rl0 * 128 + col]     = acc[mi][ni][0] + bb0 - logf(-logf(u0 + 1e-20f) + 1e-20f);
                LS[rl0 * 128 + col + 1] = acc[mi][ni][1] + bb1 - logf(-logf(u1 + 1e-20f) + 1e-20f);
            }
            {
                const float* np_ = noise + (size_t)rs[rl1] * MMZ + col;
                float u0 = np_[0], u1 = np_[1];
                LS[rl1 * 128 + col]     = acc[mi][ni][2] + bb0 - logf(-logf(u0 + 1e-20f) + 1e-20f);
                LS[rl1 * 128 + col + 1] = acc[mi][ni][3] + bb1 - logf(-logf(u1 + 1e-20f) + 1e-20f);
            }
        }
    }
    __syncthreads();

    // epilogue: dual-row interleaved per warp (ILP on shfl chains)
    for (int rp = warp; rp < 32; rp += 8) {
        int rowl[2] = {2 * rp, 2 * rp + 1};
        float v[2][4], p[2][4], t[2][4], mx[2], ssum[2], thr[2];
#pragma unroll
        for (int j = 0; j < 2; j++)
#pragma unroll
            for (int i = 0; i < 4; i++) v[j][i] = LS[rowl[j] * 128 + lane + i * 32];
#pragma unroll
        for (int j = 0; j < 2; j++)
            mx[j] = fmaxf(fmaxf(v[j][0], v[j][1]), fmaxf(v[j][2], v[j][3]));
#pragma unroll
        for (int o = 16; o > 0; o >>= 1) {
#pragma unroll
            for (int j = 0; j < 2; j++)
                mx[j] = fmaxf(mx[j], __shfl_xor_sync(0xffffffffu, mx[j], o));
        }
#pragma unroll
        for (int j = 0; j < 2; j++) {
            ssum[j] = 0.f;
#pragma unroll
            for (int i = 0; i < 4; i++) { p[j][i] = expf(v[j][i] - mx[j]); ssum[j] += p[j][i]; }
        }
#pragma unroll
        for (int o = 16; o > 0; o >>= 1) {
#pragma unroll
            for (int j = 0; j < 2; j++)
                ssum[j] += __shfl_xor_sync(0xffffffffu, ssum[j], o);
        }
#pragma unroll
        for (int j = 0; j < 2; j++) {
            float inv = 1.0f / ssum[j];
#pragma unroll
            for (int i = 0; i < 4; i++) { p[j][i] *= inv; t[j][i] = p[j][i]; }
            thr[j] = 0.f;
        }
        for (int it = 0; it < KSEL; it++) {
            float lm[2], wm[2];
#pragma unroll
            for (int j = 0; j < 2; j++)
                lm[j] = fmaxf(fmaxf(t[j][0], t[j][1]), fmaxf(t[j][2], t[j][3]));
#pragma unroll
            for (int o = 16; o > 0; o >>= 1) {
#pragma unroll
                for (int j = 0; j < 2; j++) {
                    float s2 = __shfl_xor_sync(0xffffffffu, lm[j], o);
                    lm[j] = fmaxf(lm[j], s2);
                }
            }
#pragma unroll
            for (int j = 0; j < 2; j++) wm[j] = lm[j];
            // knock out one instance per row
#pragma unroll
            for (int j = 0; j < 2; j++) {
                float lmj = fmaxf(fmaxf(t[j][0], t[j][1]), fmaxf(t[j][2], t[j][3]));
                unsigned bal = __ballot_sync(0xffffffffu, lmj == wm[j]);
                int src = __ffs(bal) - 1;
                if (lane == src) {
                    if      (t[j][0] == wm[j]) t[j][0] = -1e30f;
                    else if (t[j][1] == wm[j]) t[j][1] = -1e30f;
                    else if (t[j][2] == wm[j]) t[j][2] = -1e30f;
                    else                       t[j][3] = -1e30f;
                }
                thr[j] = wm[j];
            }
        }
#pragma unroll
        for (int j = 0; j < 2; j++) {
            int gi = tileRow + rowl[j];
            if (gi >= nact) continue;
            float* op = out + (size_t)rs[rowl[j]] * MMZ;
#pragma unroll
            for (int i = 0; i < 4; i++) {
                float z  = (p[j][i] - thr[j]) * (1.0f / 0.01f);
                float ez = expf(-fabsf(z));
                float mask = (z >= 0.f) ? 1.0f / (1.0f + ez) : ez / (1.0f + ez);
                op[lane + i * 32] = p[j][i] * mask;
            }
        }
    }
}

// ---------------------------------------------------------------------------
// Launch
// ---------------------------------------------------------------------------
extern "C" void kernel_launch(void* const* d_in, const int* in_sizes, int n_in,
                              void* d_out, int out_size) {
    int ix = -1, inoise = -1, ib1 = -1, iW2 = -1, ib2 = -1, iA = -1, iB = -1;
    for (int i = 0; i < n_in; i++) {
        int s = in_sizes[i];
        if      (s == CC * LL * EE)        ix = i;
        else if (s == RR * MMZ)            inoise = i;
        else if (s == HH)                  ib1 = i;
        else if (s == HH * MMZ)            iW2 = i;
        else if (s == MMZ)                 ib2 = i;
        else if (s == CC * LL)             { if (iA < 0) iA = i; else iB = i; }
    }
    if (ix < 0)     ix = 0;
    if (iA < 0)     iA = 1;
    if (inoise < 0) inoise = 2;
    if (iB < 0)     iB = 3;
    if (ib1 < 0)    ib1 = 4;
    if (iW2 < 0)    iW2 = 5;
    if (ib2 < 0)    ib2 = 6;

    const float* x     = (const float*)d_in[ix];
    const float* noise = (const float*)d_in[inoise];
    const float* b1    = (const float*)d_in[ib1];
    const float* W2    = (const float*)d_in[iW2];
    const float* b2    = (const float*)d_in[ib2];
    float* out = (float*)d_out;

    int write_kpm = (out_size >= RR * MMZ + RR) ? 1 : 0;

    k_detect<<<1, 256>>>((const unsigned*)d_in[iA], (const unsigned*)d_in[iB]);
    k_pack_w<<<512, 256>>>(W2);
    k_zero<<<(RR * MMZ / 4 + 255) / 256, 256>>>(out, RR * MMZ / 4);
    k_prep<<<(RR + 255) / 256, 256>>>(out + (size_t)RR * MMZ, write_kpm);
    k_pack_x<<<RRP / 2, 256>>>(x);
    k_gemm1<<<dim3(RRP / 128, 2), 256>>>(b1);
    k_gemm2<<<RRP / 64, 256>>>(b2, noise, out);
}